// round 11
// baseline (speedup 1.0000x reference)
#include <cuda_runtime.h>
#include <cuda_fp16.h>
#include <cstdint>

#define M_TOTAL 8192
#define N_TOTAL 4096
#define K_TOTAL 4096

// fp16 operands: A = fp16(x) [M][K], B = exact int4 values in fp16 [N][K]
__device__ __half g_A[(size_t)M_TOTAL * K_TOTAL];   // 64 MB
__device__ __half g_B[(size_t)N_TOTAL * K_TOTAL];   // 32 MB

// ---------------------------------------------------------------------------
// Fused prep kernel: A-convert chunks first, then B-convert chunks.
// ---------------------------------------------------------------------------
#define NA_CHUNKS ((size_t)M_TOTAL * K_TOTAL / 4)
#define NB_CHUNKS ((size_t)N_TOTAL * K_TOTAL / 4)

__global__ void __launch_bounds__(256) prep_kernel(const float4* __restrict__ x4,
                                                   const int4* __restrict__ w4) {
    size_t i = (size_t)blockIdx.x * 256 + threadIdx.x;
    if (i < NA_CHUNKS) {
        float4 v = x4[i];
        __half2* dst = (__half2*)g_A + i * 2;
        dst[0] = __floats2half2_rn(v.x, v.y);
        dst[1] = __floats2half2_rn(v.z, v.w);
    } else {
        size_t j = i - NA_CHUNKS;
        int4 q = w4[j];
        __half2* dst = (__half2*)g_B + j * 2;
        dst[0] = __floats2half2_rn((float)q.x, (float)q.y);
        dst[1] = __floats2half2_rn((float)q.z, (float)q.w);
    }
}

// ---------------------------------------------------------------------------
// Helpers
// ---------------------------------------------------------------------------
__device__ __forceinline__ uint32_t smem_u32(const void* p) {
    uint32_t a;
    asm("{ .reg .u64 t; cvta.to.shared.u64 t, %1; cvt.u32.u64 %0, t; }" : "=r"(a) : "l"(p));
    return a;
}
__device__ __forceinline__ void cp_async16(uint32_t dst, const void* src) {
    asm volatile("cp.async.cg.shared.global [%0], [%1], 16;\n" :: "r"(dst), "l"(src));
}
__device__ __forceinline__ void ldm_x4(uint32_t& d0, uint32_t& d1, uint32_t& d2, uint32_t& d3, uint32_t a) {
    asm volatile("ldmatrix.sync.aligned.m8n8.x4.shared.b16 {%0,%1,%2,%3}, [%4];\n"
                 : "=r"(d0), "=r"(d1), "=r"(d2), "=r"(d3) : "r"(a));
}
__device__ __forceinline__ void mma16816(float* c, const uint32_t* a, uint32_t b0, uint32_t b1) {
    asm volatile(
        "mma.sync.aligned.m16n8k16.row.col.f32.f16.f16.f32 "
        "{%0,%1,%2,%3}, {%4,%5,%6,%7}, {%8,%9}, {%0,%1,%2,%3};\n"
        : "+f"(c[0]), "+f"(c[1]), "+f"(c[2]), "+f"(c[3])
        : "r"(a[0]), "r"(a[1]), "r"(a[2]), "r"(a[3]), "r"(b0), "r"(b1));
}

// ---------------------------------------------------------------------------
// GEMM: CTA 128x128, BK=32, 4-stage cp.async ring, 8 warps (2M x 4N),
// warp tile 64x32. 65KB smem + launch_bounds(256,3) + carveout=100
// -> 3 CTAs/SM = 24 warps/SM = 6 warps/SMSP (sync-bubble coverage).
// Register economy: f-invariant swizzle terms, split-f A loads, x4 B loads.
// ---------------------------------------------------------------------------
#define BK 32
#define STAGES 4
#define NITER (K_TOTAL / BK)     // 128
#define STAGE 8192               // 128 rows x 64 B
#define SMEM_BYTES (2 * STAGES * STAGE + 1024)   // 66560

__global__ void __launch_bounds__(256, 3)
gemm_kernel(const float* __restrict__ wscale, const float* __restrict__ bias,
            float* __restrict__ out)
{
    extern __shared__ char smem_raw[];
    const uint32_t base = (smem_u32(smem_raw) + 1023u) & ~1023u;
    const uint32_t sAbase = base;                      // 4 x 8KB
    const uint32_t sBbase = base + STAGES * STAGE;     // 4 x 8KB

    const int tid  = threadIdx.x;
    const int lane = tid & 31;
    const int warp = tid >> 5;
    const int wm   = warp >> 2;   // 0..1
    const int wn   = warp & 3;    // 0..3
    const int bm   = blockIdx.y * 128;
    const int bn   = blockIdx.x * 128;

    // ---- producer mapping: 2 x 16B chunks per thread per operand
    const int r  = tid >> 2;          // 0..63
    const int c  = tid & 3;
    const int swz = (r >> 1) & 3;
    const uint32_t soff = (uint32_t)r * 64 + (uint32_t)((c ^ swz) << 4);

    const __half* gA = g_A + (size_t)(bm + r) * K_TOTAL + c * 8;
    const __half* gB = g_B + (size_t)(bn + r) * K_TOTAL + c * 8;

    // ---- consumer ldmatrix addressing (f-invariant swizzle!)
    // A (x4, m16k16): row(f) = wm*64 + f*16 + (lane&15); (row>>1)&3 is f-invariant.
    const uint32_t a_row0 = (uint32_t)(wm * 64 + (lane & 15)) * 64;
    const uint32_t a_sw   = (uint32_t)(((lane & 15) >> 1) & 3);
    const uint32_t a_kg   = (uint32_t)(lane >> 4);
    // B (x4 dual-n16): row(g2) = wn*32 + g2*16 + rowb, rowb=(lane&7)+((lane>>4)<<3)
    const uint32_t b_rowb = (uint32_t)((lane & 7) + ((lane >> 4) << 3));
    const uint32_t b_row0 = (uint32_t)(wn * 32 + b_rowb) * 64;
    const uint32_t b_sw   = (uint32_t)((b_rowb >> 1) & 3);
    const uint32_t b_kg   = (uint32_t)((lane >> 3) & 1);

    float acc[4][4][4];
    #pragma unroll
    for (int f = 0; f < 4; f++)
        #pragma unroll
        for (int g = 0; g < 4; g++)
            #pragma unroll
            for (int e = 0; e < 4; e++) acc[f][g][e] = 0.f;

    // ---- prologue: fill STAGES-1 slots
    #pragma unroll
    for (int s = 0; s < STAGES - 1; s++) {
        const uint32_t dA = sAbase + s * STAGE;
        const uint32_t dB = sBbase + s * STAGE;
        const int k = s * BK;
        cp_async16(dA + soff,        gA + k);
        cp_async16(dA + soff + 4096, gA + (size_t)64 * K_TOTAL + k);
        cp_async16(dB + soff,        gB + k);
        cp_async16(dB + soff + 4096, gB + (size_t)64 * K_TOTAL + k);
        asm volatile("cp.async.commit_group;\n" ::: "memory");
    }

    for (int kt = 0; kt < NITER; kt++) {
        asm volatile("cp.async.wait_group %0;\n" :: "n"(STAGES - 2) : "memory");
        __syncthreads();

        if (kt + STAGES - 1 < NITER) {
            const int s = (kt + STAGES - 1) & (STAGES - 1);
            const int k = (kt + STAGES - 1) * BK;
            const uint32_t dA = sAbase + s * STAGE;
            const uint32_t dB = sBbase + s * STAGE;
            cp_async16(dA + soff,        gA + k);
            cp_async16(dA + soff + 4096, gA + (size_t)64 * K_TOTAL + k);
            cp_async16(dB + soff,        gB + k);
            cp_async16(dB + soff + 4096, gB + (size_t)64 * K_TOTAL + k);
        }
        asm volatile("cp.async.commit_group;\n" ::: "memory");

        const int slot = kt & (STAGES - 1);
        const uint32_t sAbuf = sAbase + slot * STAGE;
        const uint32_t sBbuf = sBbase + slot * STAGE;

        #pragma unroll
        for (int ks = 0; ks < 2; ks++) {
            // B fragments for the whole ks (2 x ldm.x4 covering n32 x k16)
            uint32_t b[2][4];
            {
                const uint32_t bchunk = ((uint32_t)(ks * 2) + b_kg) ^ b_sw;
                #pragma unroll
                for (int g2 = 0; g2 < 2; g2++)
                    ldm_x4(b[g2][0], b[g2][1], b[g2][2], b[g2][3],
                           sBbuf + b_row0 + (uint32_t)g2 * 1024 + (bchunk << 4));
            }
            const uint32_t achunk = ((uint32_t)(ks * 2) + a_kg) ^ a_sw;
            // A fragments in two f-halves (keeps live A regs at 8)
            #pragma unroll
            for (int fh = 0; fh < 2; fh++) {
                uint32_t a[2][4];
                #pragma unroll
                for (int f2 = 0; f2 < 2; f2++)
                    ldm_x4(a[f2][0], a[f2][1], a[f2][2], a[f2][3],
                           sAbuf + a_row0 + (uint32_t)(fh * 2 + f2) * 1024 + (achunk << 4));
                #pragma unroll
                for (int f2 = 0; f2 < 2; f2++) {
                    #pragma unroll
                    for (int g2 = 0; g2 < 2; g2++) {
                        mma16816(acc[fh * 2 + f2][g2 * 2 + 0], a[f2], b[g2][0], b[g2][1]);
                        mma16816(acc[fh * 2 + f2][g2 * 2 + 1], a[f2], b[g2][2], b[g2][3]);
                    }
                }
            }
        }
    }

    // ---- epilogue: out = scale[n]*acc + bias[n]
    const int mrow  = bm + wm * 64 + (lane >> 2);
    const int ncol0 = bn + wn * 32 + (lane & 3) * 2;

    #pragma unroll
    for (int f = 0; f < 4; f++) {
        int r0 = mrow + f * 16;
        #pragma unroll
        for (int g = 0; g < 4; g++) {
            int col = ncol0 + g * 8;
            float sx = wscale[col], sy = wscale[col + 1];
            float bx = bias[col],   by = bias[col + 1];
            float2 v0, v1;
            v0.x = acc[f][g][0] * sx + bx;
            v0.y = acc[f][g][1] * sy + by;
            v1.x = acc[f][g][2] * sx + bx;
            v1.y = acc[f][g][3] * sy + by;
            *(float2*)(out + (size_t)r0 * N_TOTAL + col)       = v0;
            *(float2*)(out + (size_t)(r0 + 8) * N_TOTAL + col) = v1;
        }
    }
}

// ---------------------------------------------------------------------------
extern "C" void kernel_launch(void* const* d_in, const int* in_sizes, int n_in,
                              void* d_out, int out_size) {
    const float* x      = (const float*)d_in[0];
    const int*   wq     = (const int*)d_in[1];
    const float* wscale = (const float*)d_in[2];
    const float* bias   = (const float*)d_in[3];
    float*       out    = (float*)d_out;

    prep_kernel<<<(NA_CHUNKS + NB_CHUNKS) / 256, 256>>>((const float4*)x, (const int4*)wq);

    cudaFuncSetAttribute(gemm_kernel, cudaFuncAttributeMaxDynamicSharedMemorySize, SMEM_BYTES);
    // Full shared-memory carveout so THREE 65KB CTAs co-reside per SM.
    cudaFuncSetAttribute(gemm_kernel, cudaFuncAttributePreferredSharedMemoryCarveout, 100);
    dim3 grid(N_TOTAL / 128, M_TOTAL / 128);   // N fastest for B reuse in L2
    gemm_kernel<<<grid, 256, SMEM_BYTES>>>(wscale, bias, out);
}

// round 12
// speedup vs baseline: 2.0646x; 2.0646x over previous
#include <cuda_runtime.h>
#include <cuda_fp16.h>
#include <cstdint>

#define M_TOTAL 8192
#define N_TOTAL 4096
#define K_TOTAL 4096

// fp16 operands: A = fp16(x) [M][K], B = exact int4 values in fp16 [N][K]
__device__ __half g_A[(size_t)M_TOTAL * K_TOTAL];   // 64 MB
__device__ __half g_B[(size_t)N_TOTAL * K_TOTAL];   // 32 MB

// ---------------------------------------------------------------------------
// Fused prep kernel: A-convert chunks first, then B-convert chunks.
// ---------------------------------------------------------------------------
#define NA_CHUNKS ((size_t)M_TOTAL * K_TOTAL / 4)
#define NB_CHUNKS ((size_t)N_TOTAL * K_TOTAL / 4)

__global__ void __launch_bounds__(256) prep_kernel(const float4* __restrict__ x4,
                                                   const int4* __restrict__ w4) {
    size_t i = (size_t)blockIdx.x * 256 + threadIdx.x;
    if (i < NA_CHUNKS) {
        float4 v = x4[i];
        __half2* dst = (__half2*)g_A + i * 2;
        dst[0] = __floats2half2_rn(v.x, v.y);
        dst[1] = __floats2half2_rn(v.z, v.w);
    } else {
        size_t j = i - NA_CHUNKS;
        int4 q = w4[j];
        __half2* dst = (__half2*)g_B + j * 2;
        dst[0] = __floats2half2_rn((float)q.x, (float)q.y);
        dst[1] = __floats2half2_rn((float)q.z, (float)q.w);
    }
}

// ---------------------------------------------------------------------------
// Helpers
// ---------------------------------------------------------------------------
__device__ __forceinline__ uint32_t smem_u32(const void* p) {
    uint32_t a;
    asm("{ .reg .u64 t; cvta.to.shared.u64 t, %1; cvt.u32.u64 %0, t; }" : "=r"(a) : "l"(p));
    return a;
}
__device__ __forceinline__ void cp_async16(uint32_t dst, const void* src) {
    asm volatile("cp.async.cg.shared.global [%0], [%1], 16;\n" :: "r"(dst), "l"(src));
}
__device__ __forceinline__ void ldm_x4(uint32_t& d0, uint32_t& d1, uint32_t& d2, uint32_t& d3, uint32_t a) {
    asm volatile("ldmatrix.sync.aligned.m8n8.x4.shared.b16 {%0,%1,%2,%3}, [%4];\n"
                 : "=r"(d0), "=r"(d1), "=r"(d2), "=r"(d3) : "r"(a));
}
__device__ __forceinline__ void mma16816(float* c, const uint32_t* a, uint32_t b0, uint32_t b1) {
    asm volatile(
        "mma.sync.aligned.m16n8k16.row.col.f32.f16.f16.f32 "
        "{%0,%1,%2,%3}, {%4,%5,%6,%7}, {%8,%9}, {%0,%1,%2,%3};\n"
        : "+f"(c[0]), "+f"(c[1]), "+f"(c[2]), "+f"(c[3])
        : "r"(a[0]), "r"(a[1]), "r"(a[2]), "r"(a[3]), "r"(b0), "r"(b1));
}

// ---------------------------------------------------------------------------
// GEMM: CTA 128x128, BK=64, 3-stage cp.async ring, 8 warps (2M x 4N),
// warp tile 64x32. 97KB smem/CTA + carveout=100 + minBlocks=2 -> 2 CTAs/SM.
// This is the measured-best structure (tensor 74.1%). Changes this round are
// ring-index arithmetic only (no modulo in the hot loop).
// ---------------------------------------------------------------------------
#define BK 64
#define STAGES 3
#define NITER (K_TOTAL / BK)     // 64
#define OP_STAGE 16384           // 128 rows x 128 B per operand
#define SMEM_BYTES (2 * STAGES * OP_STAGE + 1024)   // 99328

__global__ void __launch_bounds__(256, 2)
gemm_kernel(const float* __restrict__ wscale, const float* __restrict__ bias,
            float* __restrict__ out)
{
    extern __shared__ char smem_raw[];
    const uint32_t base = (smem_u32(smem_raw) + 1023u) & ~1023u;
    const uint32_t sAb = base;                          // 3 x 16 KB
    const uint32_t sBb = base + STAGES * OP_STAGE;      // 3 x 16 KB

    const int tid  = threadIdx.x;
    const int lane = tid & 31;
    const int warp = tid >> 5;
    const int wm   = warp >> 2;   // 0..1
    const int wn   = warp & 3;    // 0..3
    const int bm   = blockIdx.y * 128;
    const int bn   = blockIdx.x * 128;

    // ---- producer mapping: per operand per stage, 4 rows x 16B per thread
    const int pr = tid >> 3;           // 0..31
    const int kc = tid & 7;
    const uint32_t pswz = (uint32_t)(pr & 7);
    uint32_t soff[4];
    #pragma unroll
    for (int j = 0; j < 4; j++)
        soff[j] = (uint32_t)(pr + 32 * j) * 128 + (((uint32_t)kc ^ pswz) << 4);

    const __half* gA = g_A + (size_t)(bm + pr) * K_TOTAL + kc * 8;
    const __half* gB = g_B + (size_t)(bn + pr) * K_TOTAL + kc * 8;

    // ---- A ldmatrix (x4, m16k16): f -> m row wm*64 + f*16 + (lane&15)
    const int a_kg = lane >> 4;
    uint32_t a_off[4], a_sw[4];
    #pragma unroll
    for (int f = 0; f < 4; f++) {
        int row = wm * 64 + f * 16 + (lane & 15);
        a_off[f] = (uint32_t)row * 128;
        a_sw[f]  = (uint32_t)(row & 7);
    }
    // ---- B ldmatrix (x4 covering n16 x k16)
    const int b_kc2 = (lane >> 3) & 1;
    const int b_rowb = (lane & 7) + ((lane >> 4) << 3);
    uint32_t b_off[2], b_sw[2];
    #pragma unroll
    for (int g2 = 0; g2 < 2; g2++) {
        int row = wn * 32 + g2 * 16 + b_rowb;
        b_off[g2] = (uint32_t)row * 128;
        b_sw[g2]  = (uint32_t)(row & 7);
    }

    float acc[4][4][4];
    #pragma unroll
    for (int f = 0; f < 4; f++)
        #pragma unroll
        for (int g = 0; g < 4; g++)
            #pragma unroll
            for (int e = 0; e < 4; e++) acc[f][g][e] = 0.f;

    // ---- prologue: fill STAGES-1 slots
    #pragma unroll
    for (int s = 0; s < STAGES - 1; s++) {
        const uint32_t dA = sAb + s * OP_STAGE;
        const uint32_t dB = sBb + s * OP_STAGE;
        const int k = s * BK;
        #pragma unroll
        for (int j = 0; j < 4; j++) {
            cp_async16(dA + soff[j], gA + (size_t)(32 * j) * K_TOTAL + k);
            cp_async16(dB + soff[j], gB + (size_t)(32 * j) * K_TOTAL + k);
        }
        asm volatile("cp.async.commit_group;\n" ::: "memory");
    }

    // rolling ring indices: rslot = consume slot, pslot = prefetch slot
    uint32_t rOffA = 0, pOffA = (uint32_t)(STAGES - 1) * OP_STAGE;
    int pk = (STAGES - 1) * BK;   // next k to prefetch

    for (int kt = 0; kt < NITER; kt++) {
        asm volatile("cp.async.wait_group %0;\n" :: "n"(STAGES - 2) : "memory");
        __syncthreads();

        if (pk < K_TOTAL) {
            const uint32_t dA = sAb + pOffA;
            const uint32_t dB = sBb + pOffA;
            #pragma unroll
            for (int j = 0; j < 4; j++) {
                cp_async16(dA + soff[j], gA + (size_t)(32 * j) * K_TOTAL + pk);
                cp_async16(dB + soff[j], gB + (size_t)(32 * j) * K_TOTAL + pk);
            }
            pk += BK;
            pOffA += OP_STAGE;
            if (pOffA == STAGES * OP_STAGE) pOffA = 0;
        }
        asm volatile("cp.async.commit_group;\n" ::: "memory");

        const uint32_t sAbuf = sAb + rOffA;
        const uint32_t sBbuf = sBb + rOffA;
        rOffA += OP_STAGE;
        if (rOffA == STAGES * OP_STAGE) rOffA = 0;

        #pragma unroll
        for (int ks = 0; ks < 4; ks++) {        // 4 x k16 within the 64-k tile
            uint32_t a[4][4];
            #pragma unroll
            for (int f = 0; f < 4; f++) {
                uint32_t chunk = (uint32_t)(ks * 2 + a_kg) ^ a_sw[f];
                ldm_x4(a[f][0], a[f][1], a[f][2], a[f][3],
                       sAbuf + a_off[f] + (chunk << 4));
            }
            uint32_t b[2][4];
            #pragma unroll
            for (int g2 = 0; g2 < 2; g2++) {
                uint32_t chunk = (uint32_t)(ks * 2 + b_kc2) ^ b_sw[g2];
                ldm_x4(b[g2][0], b[g2][1], b[g2][2], b[g2][3],
                       sBbuf + b_off[g2] + (chunk << 4));
            }
            #pragma unroll
            for (int f = 0; f < 4; f++) {
                #pragma unroll
                for (int g2 = 0; g2 < 2; g2++) {
                    mma16816(acc[f][g2 * 2 + 0], a[f], b[g2][0], b[g2][1]);
                    mma16816(acc[f][g2 * 2 + 1], a[f], b[g2][2], b[g2][3]);
                }
            }
        }
    }

    // ---- epilogue: out = scale[n]*acc + bias[n]
    const int mrow  = bm + wm * 64 + (lane >> 2);
    const int ncol0 = bn + wn * 32 + (lane & 3) * 2;

    #pragma unroll
    for (int f = 0; f < 4; f++) {
        int r0 = mrow + f * 16;
        #pragma unroll
        for (int g = 0; g < 4; g++) {
            int col = ncol0 + g * 8;
            float sx = wscale[col], sy = wscale[col + 1];
            float bx = bias[col],   by = bias[col + 1];
            float2 v0, v1;
            v0.x = acc[f][g][0] * sx + bx;
            v0.y = acc[f][g][1] * sy + by;
            v1.x = acc[f][g][2] * sx + bx;
            v1.y = acc[f][g][3] * sy + by;
            *(float2*)(out + (size_t)r0 * N_TOTAL + col)       = v0;
            *(float2*)(out + (size_t)(r0 + 8) * N_TOTAL + col) = v1;
        }
    }
}

// ---------------------------------------------------------------------------
extern "C" void kernel_launch(void* const* d_in, const int* in_sizes, int n_in,
                              void* d_out, int out_size) {
    const float* x      = (const float*)d_in[0];
    const int*   wq     = (const int*)d_in[1];
    const float* wscale = (const float*)d_in[2];
    const float* bias   = (const float*)d_in[3];
    float*       out    = (float*)d_out;

    prep_kernel<<<(NA_CHUNKS + NB_CHUNKS) / 256, 256>>>((const float4*)x, (const int4*)wq);

    cudaFuncSetAttribute(gemm_kernel, cudaFuncAttributeMaxDynamicSharedMemorySize, SMEM_BYTES);
    // Full 228KB carveout so TWO 97KB CTAs co-reside per SM (16 warps/SM).
    cudaFuncSetAttribute(gemm_kernel, cudaFuncAttributePreferredSharedMemoryCarveout, 100);
    dim3 grid(N_TOTAL / 128, M_TOTAL / 128);   // N fastest for B reuse in L2
    gemm_kernel<<<grid, 256, SMEM_BYTES>>>(wscale, bias, out);
}